// round 14
// baseline (speedup 1.0000x reference)
#include <cuda_runtime.h>
#include <cuda_bf16.h>

#define N_NODES 50000
#define N_EDGES 800000
#define KPTS 15
#define IN_DIM 32
#define OUT_DIM 64
#define KP_EXT 0.6f
#define BIN_CAP 32768           // per-k pair capacity (expected max ~16.3K, 2x margin)
#define PB_BLOCKS_PER_K 30
#define PB_GRID (KPTS * PB_BLOCKS_PER_K)   // 450 blocks: one wave at 4 blocks/SM

// Sparse pair bins: per kernel-point k, packed {src|dst<<16, m_bits}.
__device__ uint2  g_bins[(size_t)KPTS * BIN_CAP];        // 3.9 MB (L2-resident)
__device__ int    g_cnt[KPTS];

// ---------------------------------------------------------------------------
// Geometry: thread per edge, pos gathered directly (L2-resident, MLP-covered).
// Ball test via dot-product identity: |y-kp|^2 < R^2  <=>  y.kp2 > r2 + h_k
// with kp2 = 2*kp, h_k = |kp|^2 - R^2  (5 ops/k vs 7 for the diff form).
// Active (e,k) pairs binned by k: block-local smem counts -> one global
// atomicAdd per k per block -> scatter 8B packed entries.
// ---------------------------------------------------------------------------
__global__ __launch_bounds__(256) void k_geom(const float* __restrict__ kp,
                                              const float* __restrict__ pos,
                                              const int* __restrict__ esrc,
                                              const int* __restrict__ edst) {
    __shared__ float skp2[KPTS * 3];   // 2*kp
    __shared__ float sh[KPTS];         // |kp|^2 - R^2
    __shared__ float sq[KPTS];         // |kp|^2
    __shared__ int scnt[KPTS], sbase[KPTS];
    int tid = threadIdx.x;
    if (tid < KPTS) {
        float a = __ldg(kp + 3 * tid), b = __ldg(kp + 3 * tid + 1), c = __ldg(kp + 3 * tid + 2);
        skp2[3 * tid] = 2.f * a; skp2[3 * tid + 1] = 2.f * b; skp2[3 * tid + 2] = 2.f * c;
        float q = a * a + b * b + c * c;
        sq[tid] = q;
        sh[tid] = q - KP_EXT * KP_EXT;
        scnt[tid] = 0;
    }
    __syncthreads();

    int e = blockIdx.x * 256 + tid;
    unsigned mask = 0;
    unsigned src = 0, dst = 0;
    float y0 = 0.f, y1 = 0.f, y2 = 0.f, r2 = 0.f;
    if (e < N_EDGES) {
        src = (unsigned)__ldg(esrc + e);
        dst = (unsigned)__ldg(edst + e);
        y0 = __ldg(pos + 3 * src)     - __ldg(pos + 3 * dst);
        y1 = __ldg(pos + 3 * src + 1) - __ldg(pos + 3 * dst + 1);
        y2 = __ldg(pos + 3 * src + 2) - __ldg(pos + 3 * dst + 2);
        r2 = y0 * y0 + y1 * y1 + y2 * y2;
        #pragma unroll
        for (int k = 0; k < KPTS; k++) {
            float s2 = y0 * skp2[3 * k] + y1 * skp2[3 * k + 1] + y2 * skp2[3 * k + 2];
            if (s2 > r2 + sh[k]) mask |= (1u << k);
        }
    }

    unsigned mm = mask;
    while (mm) { int k = __ffs(mm) - 1; mm &= mm - 1; atomicAdd(&scnt[k], 1); }
    __syncthreads();
    if (tid < KPTS) { sbase[tid] = atomicAdd(&g_cnt[tid], scnt[tid]); scnt[tid] = 0; }
    __syncthreads();

    mm = mask;
    while (mm) {
        int k = __ffs(mm) - 1; mm &= mm - 1;
        int slot = sbase[k] + atomicAdd(&scnt[k], 1);
        if (slot < BIN_CAP) {
            float s2 = y0 * skp2[3 * k] + y1 * skp2[3 * k + 1] + y2 * skp2[3 * k + 2];
            float d2 = r2 - s2 + sq[k];           // |y - kp_k|^2
            d2 = fmaxf(d2, 0.f);
            float m = 1.f - sqrtf(d2) * (1.f / KP_EXT);
            if (m < 0.f) m = 0.f;
            g_bins[(size_t)k * BIN_CAP + slot] =
                make_uint2(src | (dst << 16), __float_as_uint(m));
        }
    }
}

// ---------------------------------------------------------------------------
// Apply (R9 winner, unchanged): block group per kernel point; W_k (8KB)
// smem-resident. Warp processes 4 pairs per pass; lane = h*16 + c4 owns cols
// 4*c4..+3, i-half h. Inner loop: 3x LDS.128 + 8x FFMA2 per i. One-pass
// prefetch of next bin entries + feats. shfl_xor(16) half-combine; h==0
// lanes emit red.global.add.v4.f32. lb(256,4): grid 450 <= 592 resident.
// ---------------------------------------------------------------------------
__global__ __launch_bounds__(256, 4) void k_apply(const float* __restrict__ W,
                                                  const float* __restrict__ feat,
                                                  float* __restrict__ out) {
    __shared__ __align__(16) float4 sW[IN_DIM * 16];        // [i][c4] : 8 KB
    __shared__ ulonglong2 sFd[2][8][32];                    // dup-f: 8 KB

    int k = blockIdx.x / PB_BLOCKS_PER_K;
    int blkInK = blockIdx.x - k * PB_BLOCKS_PER_K;
    int tid = threadIdx.x;

    const float4* Wk = (const float4*)(W + (size_t)k * IN_DIM * OUT_DIM);
    sW[tid]       = __ldg(Wk + tid);
    sW[tid + 256] = __ldg(Wk + tid + 256);
    __syncthreads();

    int cnt = g_cnt[k];
    cnt = (cnt < BIN_CAP) ? cnt : BIN_CAP;
    if (cnt <= 0) return;

    int lane = tid & 31, wl = tid >> 5;
    int h = lane >> 4, c4 = lane & 15;
    const uint2* bin = g_bins + (size_t)k * BIN_CAP;
    const ulonglong2* sW2 = (const ulonglong2*)sW;
    const int STRIDE = PB_BLOCKS_PER_K * 8 * 4;
    int base = (blkInK * 8 + wl) * 4;

    int   curD[4];
    float curF[4];
    #pragma unroll
    for (int p = 0; p < 4; p++) {
        int idx = base + p;
        if (idx < cnt) {
            uint2 e = __ldg(bin + idx);                        // broadcast
            unsigned sp = e.x & 0xFFFFu;
            curD[p] = (int)(e.x >> 16);
            curF[p] = __ldg(feat + (size_t)sp * IN_DIM + lane) * __uint_as_float(e.y);
        } else { curD[p] = -1; curF[p] = 0.f; }
    }

    for (; base < cnt; base += STRIDE) {
        // ---- stage pre-duplicated f: 2 conflict-free STS.128 ----
        ulonglong2 v0, v1;
        asm("mov.b64 %0, {%1,%1};" : "=l"(v0.x) : "r"(__float_as_uint(curF[0])));
        asm("mov.b64 %0, {%1,%1};" : "=l"(v0.y) : "r"(__float_as_uint(curF[1])));
        asm("mov.b64 %0, {%1,%1};" : "=l"(v1.x) : "r"(__float_as_uint(curF[2])));
        asm("mov.b64 %0, {%1,%1};" : "=l"(v1.y) : "r"(__float_as_uint(curF[3])));
        sFd[0][wl][lane] = v0;
        sFd[1][wl][lane] = v1;
        __syncwarp();

        // ---- prefetch next pass (independent LDGs, hidden under compute) --
        int nD[4]; float nF[4];
        int nb = base + STRIDE;
        #pragma unroll
        for (int p = 0; p < 4; p++) {
            int idx = nb + p;
            if (idx < cnt) {
                uint2 e = __ldg(bin + idx);
                unsigned sp = e.x & 0xFFFFu;
                nD[p] = (int)(e.x >> 16);
                nF[p] = __ldg(feat + (size_t)sp * IN_DIM + lane) * __uint_as_float(e.y);
            } else { nD[p] = -1; nF[p] = 0.f; }
        }

        // ---- compute: per i = 3 LDS.128 + 8 FFMA2, no movs ----
        unsigned long long a01[4] = {0,0,0,0}, a23[4] = {0,0,0,0};
        #pragma unroll
        for (int s = 0; s < 16; s++) {
            int i = s + 16 * h;
            ulonglong2 w   = sW2[i * 16 + c4];      // (w0,w1),(w2,w3) packed
            ulonglong2 F01 = sFd[0][wl][i];         // (f0,f0),(f1,f1)
            ulonglong2 F23 = sFd[1][wl][i];         // (f2,f2),(f3,f3)
            asm("fma.rn.f32x2 %0, %1, %2, %0;" : "+l"(a01[0]) : "l"(F01.x), "l"(w.x));
            asm("fma.rn.f32x2 %0, %1, %2, %0;" : "+l"(a23[0]) : "l"(F01.x), "l"(w.y));
            asm("fma.rn.f32x2 %0, %1, %2, %0;" : "+l"(a01[1]) : "l"(F01.y), "l"(w.x));
            asm("fma.rn.f32x2 %0, %1, %2, %0;" : "+l"(a23[1]) : "l"(F01.y), "l"(w.y));
            asm("fma.rn.f32x2 %0, %1, %2, %0;" : "+l"(a01[2]) : "l"(F23.x), "l"(w.x));
            asm("fma.rn.f32x2 %0, %1, %2, %0;" : "+l"(a23[2]) : "l"(F23.x), "l"(w.y));
            asm("fma.rn.f32x2 %0, %1, %2, %0;" : "+l"(a01[3]) : "l"(F23.y), "l"(w.x));
            asm("fma.rn.f32x2 %0, %1, %2, %0;" : "+l"(a23[3]) : "l"(F23.y), "l"(w.y));
        }
        __syncwarp();   // sFd reads done before next pass overwrites

        // ---- reduce halves + REDG ----
        #pragma unroll
        for (int p = 0; p < 4; p++) {
            if (curD[p] < 0) continue;              // warp-uniform (broadcast)
            unsigned x0, x1, x2, x3;
            asm("mov.b64 {%0,%1}, %2;" : "=r"(x0), "=r"(x1) : "l"(a01[p]));
            asm("mov.b64 {%0,%1}, %2;" : "=r"(x2), "=r"(x3) : "l"(a23[p]));
            float v0f = __uint_as_float(x0), v1f = __uint_as_float(x1);
            float v2f = __uint_as_float(x2), v3f = __uint_as_float(x3);
            v0f += __shfl_xor_sync(0xffffffffu, v0f, 16);
            v1f += __shfl_xor_sync(0xffffffffu, v1f, 16);
            v2f += __shfl_xor_sync(0xffffffffu, v2f, 16);
            v3f += __shfl_xor_sync(0xffffffffu, v3f, 16);
            if (h == 0) {
                float* dp = out + (size_t)curD[p] * OUT_DIM + c4 * 4;
                asm volatile("red.global.add.v4.f32 [%0], {%1,%2,%3,%4};"
                             :: "l"(dp), "f"(v0f), "f"(v1f), "f"(v2f), "f"(v3f)
                             : "memory");
            }
        }

        // ---- rotate prefetch ----
        #pragma unroll
        for (int p = 0; p < 4; p++) { curD[p] = nD[p]; curF[p] = nF[p]; }
    }
}

extern "C" void kernel_launch(void* const* d_in, const int* in_sizes, int n_in,
                              void* d_out, int out_size) {
    const float* pos  = (const float*)d_in[0];
    const float* feat = (const float*)d_in[1];
    const float* kp   = (const float*)d_in[2];
    const float* W    = (const float*)d_in[3];
    const int*   esrc = (const int*)d_in[4];
    const int*   edst = (const int*)d_in[5];
    float* out = (float*)d_out;

    void* cntAddr = nullptr;
    cudaGetSymbolAddress(&cntAddr, g_cnt);        // host-side query, capture-safe
    cudaMemsetAsync(cntAddr, 0, KPTS * sizeof(int));
    cudaMemsetAsync(out, 0, (size_t)out_size * sizeof(float));
    k_geom<<<(N_EDGES + 255) / 256, 256>>>(kp, pos, esrc, edst);
    k_apply<<<PB_GRID, 256>>>(W, feat, out);
}

// round 15
// speedup vs baseline: 1.0586x; 1.0586x over previous
#include <cuda_runtime.h>
#include <cuda_bf16.h>

#define N_NODES 50000
#define N_EDGES 800000
#define KPTS 15
#define IN_DIM 32
#define OUT_DIM 64
#define KP_EXT 0.6f
#define BIN_CAP 32768           // per-k pair capacity (expected max ~16.3K, 2x margin)
#define PB_BLOCKS_PER_K 29
#define PB_GRID (KPTS * PB_BLOCKS_PER_K)   // 435 blocks: one wave at 3 blocks/SM

// Sparse pair bins: per kernel-point k, packed {src|dst<<16, m_bits}.
__device__ float4 g_pos4[N_NODES];                       // 0.8 MB
__device__ uint2  g_bins[(size_t)KPTS * BIN_CAP];        // 3.9 MB (L2-resident)
__device__ int    g_cnt[KPTS];

// ---------------------------------------------------------------------------
// Prep: pack pos to float4 (halves geom's gather sectors), reset counters.
// ---------------------------------------------------------------------------
__global__ __launch_bounds__(256) void k_prep(const float* __restrict__ pos) {
    int i = blockIdx.x * 256 + threadIdx.x;
    if (i < KPTS) g_cnt[i] = 0;
    if (i < N_NODES)
        g_pos4[i] = make_float4(__ldg(pos + 3 * i), __ldg(pos + 3 * i + 1),
                                __ldg(pos + 3 * i + 2), 0.f);
}

// ---------------------------------------------------------------------------
// Geometry: thread per edge, pos gathered as packed float4 (2 sectors/edge).
// Ball test via dot-product identity: |y-kp|^2 < R^2  <=>  y.kp2 > r2 + h_k
// with kp2 = 2*kp, h_k = |kp|^2 - R^2. Active (e,k) pairs binned by k:
// block-local smem counts -> one global atomicAdd per k per block -> scatter.
// ---------------------------------------------------------------------------
__global__ __launch_bounds__(256) void k_geom(const float* __restrict__ kp,
                                              const int* __restrict__ esrc,
                                              const int* __restrict__ edst) {
    __shared__ float skp2[KPTS * 3];   // 2*kp
    __shared__ float sh[KPTS];         // |kp|^2 - R^2
    __shared__ float sq[KPTS];         // |kp|^2
    __shared__ int scnt[KPTS], sbase[KPTS];
    int tid = threadIdx.x;
    if (tid < KPTS) {
        float a = __ldg(kp + 3 * tid), b = __ldg(kp + 3 * tid + 1), c = __ldg(kp + 3 * tid + 2);
        skp2[3 * tid] = 2.f * a; skp2[3 * tid + 1] = 2.f * b; skp2[3 * tid + 2] = 2.f * c;
        float q = a * a + b * b + c * c;
        sq[tid] = q;
        sh[tid] = q - KP_EXT * KP_EXT;
        scnt[tid] = 0;
    }
    __syncthreads();

    int e = blockIdx.x * 256 + tid;
    unsigned mask = 0;
    unsigned src = 0, dst = 0;
    float y0 = 0.f, y1 = 0.f, y2 = 0.f, r2 = 0.f;
    if (e < N_EDGES) {
        src = (unsigned)__ldg(esrc + e);
        dst = (unsigned)__ldg(edst + e);
        float4 ps = g_pos4[src], pd = g_pos4[dst];
        y0 = ps.x - pd.x; y1 = ps.y - pd.y; y2 = ps.z - pd.z;
        r2 = y0 * y0 + y1 * y1 + y2 * y2;
        #pragma unroll
        for (int k = 0; k < KPTS; k++) {
            float s2 = y0 * skp2[3 * k] + y1 * skp2[3 * k + 1] + y2 * skp2[3 * k + 2];
            if (s2 > r2 + sh[k]) mask |= (1u << k);
        }
    }

    unsigned mm = mask;
    while (mm) { int k = __ffs(mm) - 1; mm &= mm - 1; atomicAdd(&scnt[k], 1); }
    __syncthreads();
    if (tid < KPTS) { sbase[tid] = atomicAdd(&g_cnt[tid], scnt[tid]); scnt[tid] = 0; }
    __syncthreads();

    mm = mask;
    while (mm) {
        int k = __ffs(mm) - 1; mm &= mm - 1;
        int slot = sbase[k] + atomicAdd(&scnt[k], 1);
        if (slot < BIN_CAP) {
            float s2 = y0 * skp2[3 * k] + y1 * skp2[3 * k + 1] + y2 * skp2[3 * k + 2];
            float d2 = fmaxf(r2 - s2 + sq[k], 0.f);     // |y - kp_k|^2
            float m = fmaxf(1.f - sqrtf(d2) * (1.f / KP_EXT), 0.f);
            g_bins[(size_t)k * BIN_CAP + slot] =
                make_uint2(src | (dst << 16), __float_as_uint(m));
        }
    }
}

// ---------------------------------------------------------------------------
// Apply: block group per kernel point; W_k (8KB) smem-resident. Warp now
// processes EIGHT pairs per pass, halving W-tile smem wavefronts per pair
// (the L1TEX-bound term per the R14 profile). Lane = h*16 + c4 owns cols
// 4*c4..+3, i-half h. Inner loop per i: 1x W LDS.128 + 4x broadcast LDS.128
// + 16x FFMA2. One-pass prefetch of next 8 entries+feats. shfl_xor(16)
// half-combine; h==0 lanes emit red.global.add.v4.f32 per pair.
// ---------------------------------------------------------------------------
#define PAIRS 8
__global__ __launch_bounds__(256, 3) void k_apply(const float* __restrict__ W,
                                                  const float* __restrict__ feat,
                                                  float* __restrict__ out) {
    __shared__ __align__(16) float4 sW[IN_DIM * 16];        // [i][c4] : 8 KB
    __shared__ ulonglong2 sFd[4][8][32];                    // dup-f: 16 KB

    int k = blockIdx.x / PB_BLOCKS_PER_K;
    int blkInK = blockIdx.x - k * PB_BLOCKS_PER_K;
    int tid = threadIdx.x;

    const float4* Wk = (const float4*)(W + (size_t)k * IN_DIM * OUT_DIM);
    sW[tid]       = __ldg(Wk + tid);
    sW[tid + 256] = __ldg(Wk + tid + 256);
    __syncthreads();

    int cnt = g_cnt[k];
    cnt = (cnt < BIN_CAP) ? cnt : BIN_CAP;
    if (cnt <= 0) return;

    int lane = tid & 31, wl = tid >> 5;
    int h = lane >> 4, c4 = lane & 15;
    const uint2* bin = g_bins + (size_t)k * BIN_CAP;
    const ulonglong2* sW2 = (const ulonglong2*)sW;
    const int STRIDE = PB_BLOCKS_PER_K * 8 * PAIRS;
    int base = (blkInK * 8 + wl) * PAIRS;

    int   curD[PAIRS];
    float curF[PAIRS];
    #pragma unroll
    for (int p = 0; p < PAIRS; p++) {
        int idx = base + p;
        if (idx < cnt) {
            uint2 e = __ldg(bin + idx);                        // broadcast
            unsigned sp = e.x & 0xFFFFu;
            curD[p] = (int)(e.x >> 16);
            curF[p] = __ldg(feat + (size_t)sp * IN_DIM + lane) * __uint_as_float(e.y);
        } else { curD[p] = -1; curF[p] = 0.f; }
    }

    for (; base < cnt; base += STRIDE) {
        // ---- stage pre-duplicated f: 4 conflict-free STS.128 ----
        #pragma unroll
        for (int q = 0; q < 4; q++) {
            ulonglong2 v;
            asm("mov.b64 %0, {%1,%1};" : "=l"(v.x) : "r"(__float_as_uint(curF[2 * q])));
            asm("mov.b64 %0, {%1,%1};" : "=l"(v.y) : "r"(__float_as_uint(curF[2 * q + 1])));
            sFd[q][wl][lane] = v;
        }
        __syncwarp();

        // ---- prefetch next pass (independent LDGs, hidden under compute) --
        int nD[PAIRS]; float nF[PAIRS];
        int nb = base + STRIDE;
        #pragma unroll
        for (int p = 0; p < PAIRS; p++) {
            int idx = nb + p;
            if (idx < cnt) {
                uint2 e = __ldg(bin + idx);
                unsigned sp = e.x & 0xFFFFu;
                nD[p] = (int)(e.x >> 16);
                nF[p] = __ldg(feat + (size_t)sp * IN_DIM + lane) * __uint_as_float(e.y);
            } else { nD[p] = -1; nF[p] = 0.f; }
        }

        // ---- compute: per i = 5 LDS.128 + 16 FFMA2 ----
        unsigned long long a01[PAIRS], a23[PAIRS];
        #pragma unroll
        for (int p = 0; p < PAIRS; p++) { a01[p] = 0ull; a23[p] = 0ull; }
        #pragma unroll
        for (int s = 0; s < 16; s++) {
            int i = s + 16 * h;
            ulonglong2 w = sW2[i * 16 + c4];        // (w0,w1),(w2,w3) packed
            #pragma unroll
            for (int q = 0; q < 4; q++) {
                ulonglong2 F = sFd[q][wl][i];       // (f2q,f2q),(f2q+1,f2q+1)
                asm("fma.rn.f32x2 %0, %1, %2, %0;" : "+l"(a01[2 * q])     : "l"(F.x), "l"(w.x));
                asm("fma.rn.f32x2 %0, %1, %2, %0;" : "+l"(a23[2 * q])     : "l"(F.x), "l"(w.y));
                asm("fma.rn.f32x2 %0, %1, %2, %0;" : "+l"(a01[2 * q + 1]) : "l"(F.y), "l"(w.x));
                asm("fma.rn.f32x2 %0, %1, %2, %0;" : "+l"(a23[2 * q + 1]) : "l"(F.y), "l"(w.y));
            }
        }
        __syncwarp();   // sFd reads done before next pass overwrites

        // ---- reduce halves + REDG ----
        #pragma unroll
        for (int p = 0; p < PAIRS; p++) {
            if (curD[p] < 0) continue;              // warp-uniform (broadcast)
            unsigned x0, x1, x2, x3;
            asm("mov.b64 {%0,%1}, %2;" : "=r"(x0), "=r"(x1) : "l"(a01[p]));
            asm("mov.b64 {%0,%1}, %2;" : "=r"(x2), "=r"(x3) : "l"(a23[p]));
            float v0f = __uint_as_float(x0), v1f = __uint_as_float(x1);
            float v2f = __uint_as_float(x2), v3f = __uint_as_float(x3);
            v0f += __shfl_xor_sync(0xffffffffu, v0f, 16);
            v1f += __shfl_xor_sync(0xffffffffu, v1f, 16);
            v2f += __shfl_xor_sync(0xffffffffu, v2f, 16);
            v3f += __shfl_xor_sync(0xffffffffu, v3f, 16);
            if (h == 0) {
                float* dp = out + (size_t)curD[p] * OUT_DIM + c4 * 4;
                asm volatile("red.global.add.v4.f32 [%0], {%1,%2,%3,%4};"
                             :: "l"(dp), "f"(v0f), "f"(v1f), "f"(v2f), "f"(v3f)
                             : "memory");
            }
        }

        // ---- rotate prefetch ----
        #pragma unroll
        for (int p = 0; p < PAIRS; p++) { curD[p] = nD[p]; curF[p] = nF[p]; }
    }
}

extern "C" void kernel_launch(void* const* d_in, const int* in_sizes, int n_in,
                              void* d_out, int out_size) {
    const float* pos  = (const float*)d_in[0];
    const float* feat = (const float*)d_in[1];
    const float* kp   = (const float*)d_in[2];
    const float* W    = (const float*)d_in[3];
    const int*   esrc = (const int*)d_in[4];
    const int*   edst = (const int*)d_in[5];
    float* out = (float*)d_out;

    cudaMemsetAsync(out, 0, (size_t)out_size * sizeof(float));
    k_prep<<<(N_NODES + 255) / 256, 256>>>(pos);
    k_geom<<<(N_EDGES + 255) / 256, 256>>>(kp, esrc, edst);
    k_apply<<<PB_GRID, 256>>>(W, feat, out);
}

// round 17
// speedup vs baseline: 1.1051x; 1.0439x over previous
#include <cuda_runtime.h>
#include <cuda_bf16.h>

#define N_NODES 50000
#define N_EDGES 800000
#define KPTS 15
#define IN_DIM 32
#define OUT_DIM 64
#define KP_EXT 0.6f
#define BIN_CAP 32768           // per-k pair capacity (expected max ~16.3K, 2x margin)
#define PB_BLOCKS_PER_K 19
#define PB_GRID (KPTS * PB_BLOCKS_PER_K)   // 285 blocks: one wave at 2 blocks/SM
#define PAIRS 4

// Sparse pair bins: per kernel-point k, packed {src|dst<<16, m_bits}.
__device__ float4 g_pos4[N_NODES];                       // 0.8 MB
__device__ uint2  g_bins[(size_t)KPTS * BIN_CAP];        // 3.9 MB (L2-resident)
__device__ int    g_cnt[KPTS];

// ---------------------------------------------------------------------------
// Prep: pack pos to float4 (halves geom's gather sectors), reset counters.
// ---------------------------------------------------------------------------
__global__ __launch_bounds__(256) void k_prep(const float* __restrict__ pos) {
    int i = blockIdx.x * 256 + threadIdx.x;
    if (i < KPTS) g_cnt[i] = 0;
    if (i < N_NODES)
        g_pos4[i] = make_float4(__ldg(pos + 3 * i), __ldg(pos + 3 * i + 1),
                                __ldg(pos + 3 * i + 2), 0.f);
}

// ---------------------------------------------------------------------------
// Geometry: TWO edges per thread (doubles gather MLP, halves warp count).
// Ball test via dot identity: |y-kp|^2 < R^2  <=>  y.(2kp) > r2 + |kp|^2-R^2.
// Active (e,k) pairs binned by k: block-local smem counts -> one global
// atomicAdd per k per block -> scatter 8B packed entries.
// ---------------------------------------------------------------------------
__global__ __launch_bounds__(256) void k_geom(const float* __restrict__ kp,
                                              const int* __restrict__ esrc,
                                              const int* __restrict__ edst) {
    __shared__ float skp2[KPTS * 3];   // 2*kp
    __shared__ float sh[KPTS];         // |kp|^2 - R^2
    __shared__ float sq[KPTS];         // |kp|^2
    __shared__ int scnt[KPTS], sbase[KPTS];
    int tid = threadIdx.x;
    if (tid < KPTS) {
        float a = __ldg(kp + 3 * tid), b = __ldg(kp + 3 * tid + 1), c = __ldg(kp + 3 * tid + 2);
        skp2[3 * tid] = 2.f * a; skp2[3 * tid + 1] = 2.f * b; skp2[3 * tid + 2] = 2.f * c;
        float q = a * a + b * b + c * c;
        sq[tid] = q;
        sh[tid] = q - KP_EXT * KP_EXT;
        scnt[tid] = 0;
    }
    __syncthreads();

    unsigned mask[2] = {0, 0};
    unsigned src[2] = {0, 0}, dst[2] = {0, 0};
    float y0[2], y1[2], y2[2], r2[2];

    #pragma unroll
    for (int j = 0; j < 2; j++) {
        int e = blockIdx.x * 512 + j * 256 + tid;
        y0[j] = y1[j] = y2[j] = r2[j] = 0.f;
        if (e < N_EDGES) {
            src[j] = (unsigned)__ldg(esrc + e);
            dst[j] = (unsigned)__ldg(edst + e);
            float4 ps = g_pos4[src[j]], pd = g_pos4[dst[j]];
            y0[j] = ps.x - pd.x; y1[j] = ps.y - pd.y; y2[j] = ps.z - pd.z;
            r2[j] = y0[j] * y0[j] + y1[j] * y1[j] + y2[j] * y2[j];
            #pragma unroll
            for (int k = 0; k < KPTS; k++) {
                float s2 = y0[j] * skp2[3 * k] + y1[j] * skp2[3 * k + 1] + y2[j] * skp2[3 * k + 2];
                if (s2 > r2[j] + sh[k]) mask[j] |= (1u << k);
            }
        }
    }

    #pragma unroll
    for (int j = 0; j < 2; j++) {
        unsigned mm = mask[j];
        while (mm) { int k = __ffs(mm) - 1; mm &= mm - 1; atomicAdd(&scnt[k], 1); }
    }
    __syncthreads();
    if (tid < KPTS) { sbase[tid] = atomicAdd(&g_cnt[tid], scnt[tid]); scnt[tid] = 0; }
    __syncthreads();

    #pragma unroll
    for (int j = 0; j < 2; j++) {
        unsigned mm = mask[j];
        while (mm) {
            int k = __ffs(mm) - 1; mm &= mm - 1;
            int slot = sbase[k] + atomicAdd(&scnt[k], 1);
            if (slot < BIN_CAP) {
                float s2 = y0[j] * skp2[3 * k] + y1[j] * skp2[3 * k + 1] + y2[j] * skp2[3 * k + 2];
                float d2 = fmaxf(r2[j] - s2 + sq[k], 0.f);     // |y - kp_k|^2
                float m = fmaxf(1.f - sqrtf(d2) * (1.f / KP_EXT), 0.f);
                g_bins[(size_t)k * BIN_CAP + slot] =
                    make_uint2(src[j] | (dst[j] << 16), __float_as_uint(m));
            }
        }
    }
}

// ---------------------------------------------------------------------------
// Apply: block group per kernel point. W_k slice held in REGISTERS per lane
// (16x LDG.128 once; lane = h*16+c4 owns cols 4*c4..+3, i-half h). Inner
// loop per i: 2x broadcast LDS.128 + 8x FFMA2 — no W smem traffic, no block
// syncs. The LSU port is left to the irreducible terms: REDG (16 lanes x
// 16B per pair), f broadcasts, feat/bin gathers. One-pass prefetch of next
// entries+feats. shfl_xor(16) half-combine; h==0 lanes emit one
// red.global.add.v4.f32 per pair. lb(256,2): grid 285 <= 296 = one wave.
// ---------------------------------------------------------------------------
__global__ __launch_bounds__(256, 2) void k_apply(const float* __restrict__ W,
                                                  const float* __restrict__ feat,
                                                  float* __restrict__ out) {
    __shared__ ulonglong2 sFd[2][8][32];                    // dup-f: 8 KB

    int k = blockIdx.x / PB_BLOCKS_PER_K;
    int blkInK = blockIdx.x - k * PB_BLOCKS_PER_K;
    int tid = threadIdx.x;
    int lane = tid & 31, wl = tid >> 5;
    int h = lane >> 4, c4 = lane & 15;

    // ---- preload this lane's W slice into registers (32 ullong = 64 regs) --
    const ulonglong2* Wg = (const ulonglong2*)(W + (size_t)k * IN_DIM * OUT_DIM);
    ulonglong2 wreg[16];
    #pragma unroll
    for (int s = 0; s < 16; s++)
        wreg[s] = __ldg(Wg + (size_t)(s + 16 * h) * 16 + c4);

    int cnt = g_cnt[k];
    cnt = (cnt < BIN_CAP) ? cnt : BIN_CAP;
    if (cnt <= 0) return;

    const uint2* bin = g_bins + (size_t)k * BIN_CAP;
    const int STRIDE = PB_BLOCKS_PER_K * 8 * PAIRS;
    int base = (blkInK * 8 + wl) * PAIRS;

    int   curD[PAIRS];
    float curF[PAIRS];
    #pragma unroll
    for (int p = 0; p < PAIRS; p++) {
        int idx = base + p;
        if (idx < cnt) {
            uint2 e = __ldg(bin + idx);                        // broadcast
            unsigned sp = e.x & 0xFFFFu;
            curD[p] = (int)(e.x >> 16);
            curF[p] = __ldg(feat + (size_t)sp * IN_DIM + lane) * __uint_as_float(e.y);
        } else { curD[p] = -1; curF[p] = 0.f; }
    }

    for (; base < cnt; base += STRIDE) {
        // ---- stage pre-duplicated f: 2 conflict-free STS.128 ----
        ulonglong2 v0, v1;
        asm("mov.b64 %0, {%1,%1};" : "=l"(v0.x) : "r"(__float_as_uint(curF[0])));
        asm("mov.b64 %0, {%1,%1};" : "=l"(v0.y) : "r"(__float_as_uint(curF[1])));
        asm("mov.b64 %0, {%1,%1};" : "=l"(v1.x) : "r"(__float_as_uint(curF[2])));
        asm("mov.b64 %0, {%1,%1};" : "=l"(v1.y) : "r"(__float_as_uint(curF[3])));
        sFd[0][wl][lane] = v0;
        sFd[1][wl][lane] = v1;
        __syncwarp();

        // ---- prefetch next pass (independent LDGs, hidden under compute) --
        int nD[PAIRS]; float nF[PAIRS];
        int nb = base + STRIDE;
        #pragma unroll
        for (int p = 0; p < PAIRS; p++) {
            int idx = nb + p;
            if (idx < cnt) {
                uint2 e = __ldg(bin + idx);
                unsigned sp = e.x & 0xFFFFu;
                nD[p] = (int)(e.x >> 16);
                nF[p] = __ldg(feat + (size_t)sp * IN_DIM + lane) * __uint_as_float(e.y);
            } else { nD[p] = -1; nF[p] = 0.f; }
        }

        // ---- compute: per i = 2 broadcast LDS.128 + 8 FFMA2 (W in regs) ---
        unsigned long long a01[PAIRS], a23[PAIRS];
        #pragma unroll
        for (int p = 0; p < PAIRS; p++) { a01[p] = 0ull; a23[p] = 0ull; }
        #pragma unroll
        for (int s = 0; s < 16; s++) {
            int i = s + 16 * h;
            ulonglong2 w = wreg[s];
            ulonglong2 F01 = sFd[0][wl][i];         // (f0,f0),(f1,f1)
            ulonglong2 F23 = sFd[1][wl][i];         // (f2,f2),(f3,f3)
            asm("fma.rn.f32x2 %0, %1, %2, %0;" : "+l"(a01[0]) : "l"(F01.x), "l"(w.x));
            asm("fma.rn.f32x2 %0, %1, %2, %0;" : "+l"(a23[0]) : "l"(F01.x), "l"(w.y));
            asm("fma.rn.f32x2 %0, %1, %2, %0;" : "+l"(a01[1]) : "l"(F01.y), "l"(w.x));
            asm("fma.rn.f32x2 %0, %1, %2, %0;" : "+l"(a23[1]) : "l"(F01.y), "l"(w.y));
            asm("fma.rn.f32x2 %0, %1, %2, %0;" : "+l"(a01[2]) : "l"(F23.x), "l"(w.x));
            asm("fma.rn.f32x2 %0, %1, %2, %0;" : "+l"(a23[2]) : "l"(F23.x), "l"(w.y));
            asm("fma.rn.f32x2 %0, %1, %2, %0;" : "+l"(a01[3]) : "l"(F23.y), "l"(w.x));
            asm("fma.rn.f32x2 %0, %1, %2, %0;" : "+l"(a23[3]) : "l"(F23.y), "l"(w.y));
        }
        __syncwarp();   // sFd reads done before next pass overwrites

        // ---- reduce halves + REDG ----
        #pragma unroll
        for (int p = 0; p < PAIRS; p++) {
            if (curD[p] < 0) continue;              // warp-uniform (broadcast)
            unsigned x0, x1, x2, x3;
            asm("mov.b64 {%0,%1}, %2;" : "=r"(x0), "=r"(x1) : "l"(a01[p]));
            asm("mov.b64 {%0,%1}, %2;" : "=r"(x2), "=r"(x3) : "l"(a23[p]));
            float v0f = __uint_as_float(x0), v1f = __uint_as_float(x1);
            float v2f = __uint_as_float(x2), v3f = __uint_as_float(x3);
            v0f += __shfl_xor_sync(0xffffffffu, v0f, 16);
            v1f += __shfl_xor_sync(0xffffffffu, v1f, 16);
            v2f += __shfl_xor_sync(0xffffffffu, v2f, 16);
            v3f += __shfl_xor_sync(0xffffffffu, v3f, 16);
            if (h == 0) {
                float* dp = out + (size_t)curD[p] * OUT_DIM + c4 * 4;
                asm volatile("red.global.add.v4.f32 [%0], {%1,%2,%3,%4};"
                             :: "l"(dp), "f"(v0f), "f"(v1f), "f"(v2f), "f"(v3f)
                             : "memory");
            }
        }

        // ---- rotate prefetch ----
        #pragma unroll
        for (int p = 0; p < PAIRS; p++) { curD[p] = nD[p]; curF[p] = nF[p]; }
    }
}

extern "C" void kernel_launch(void* const* d_in, const int* in_sizes, int n_in,
                              void* d_out, int out_size) {
    const float* pos  = (const float*)d_in[0];
    const float* feat = (const float*)d_in[1];
    const float* kp   = (const float*)d_in[2];
    const float* W    = (const float*)d_in[3];
    const int*   esrc = (const int*)d_in[4];
    const int*   edst = (const int*)d_in[5];
    float* out = (float*)d_out;

    cudaMemsetAsync(out, 0, (size_t)out_size * sizeof(float));
    k_prep<<<(N_NODES + 255) / 256, 256>>>(pos);
    k_geom<<<(N_EDGES + 511) / 512, 256>>>(kp, esrc, edst);
    k_apply<<<PB_GRID, 256>>>(W, feat, out);
}